// round 10
// baseline (speedup 1.0000x reference)
#include <cuda_runtime.h>
#include <cstdint>

#define DDIM   768
#define D4     192      // DDIM / 4
#define KCL    500
#define KTILE  10       // 50 tiles exactly
#define NTHR   256

// ---------------------------------------------------------------------------
// Block = 256 threads = 256 consecutive points.
//   Phase 1: c_sq[k] = round_to_f32( sum_f64( fl32(c_i * c_i) ) )  (all 500)
//   Phase 2: x_sq    = round_to_f32( sum_f64( fl32(x_i * x_i) ) )  (own row)
//   Phase 3: tiles of 10 clusters; dot via 4 independent per-component fp32
//            chains; decision replicates reference elementwise fp32 ops:
//               d = max( (x_sq + c_sq) - 2*cross , 0 )   [sqrt monotone]
// First-occurrence tie-break: ascending k, strict <.
// Output: argmin index as float32 (harness __output__ dtype).
// ---------------------------------------------------------------------------
__global__ __launch_bounds__(NTHR)
void kmeans_simple_kernel(const float* __restrict__ F,
                          const float* __restrict__ C,
                          float* __restrict__ out, int N) {
    __shared__ float4 cs[KTILE][D4];   // 30720 B
    __shared__ float  scq[KCL];        //  2000 B

    const int tid = threadIdx.x;
    const int p   = blockIdx.x * NTHR + tid;
    const bool valid = (p < N);
    const long pl = valid ? (long)p : 0;   // clamped row for safe loads

    const float4* F4 = (const float4*)F;
    const float4* C4 = (const float4*)C;

    // ---- Phase 1: cluster squared norms, fp64-accumulated fp32 squares ----
    for (int k = tid; k < KCL; k += NTHR) {
        double s = 0.0;
        const float4* row = C4 + (long)k * D4;
#pragma unroll 4
        for (int i = 0; i < D4; i++) {
            float4 v = row[i];
            // squares rounded to fp32 first (matches reference's x*x HLO),
            // then summed exactly in fp64
            s += (double)(v.x * v.x);
            s += (double)(v.y * v.y);
            s += (double)(v.z * v.z);
            s += (double)(v.w * v.w);
        }
        scq[k] = (float)s;
    }
    __syncthreads();

    // ---- Phase 2: own-point squared norm, same scheme ----
    float xsq;
    {
        double s = 0.0;
        const float4* frow = F4 + pl * D4;
#pragma unroll 4
        for (int i = 0; i < D4; i++) {
            float4 v = frow[i];
            s += (double)(v.x * v.x);
            s += (double)(v.y * v.y);
            s += (double)(v.z * v.z);
            s += (double)(v.w * v.w);
        }
        xsq = (float)s;
    }

    // ---- Phase 3: tiles of 10 clusters ----
    float best = 3.402823466e38f;
    int   bidx = 0;

    for (int k0 = 0; k0 < KCL; k0 += KTILE) {
        __syncthreads();   // previous tile fully consumed
        for (int s = tid; s < KTILE * D4; s += NTHR) {
            int kk = s / D4;
            int ii = s - kk * D4;
            cs[kk][ii] = C4[(long)(k0 + kk) * D4 + ii];
        }
        __syncthreads();

        // 4 independent fp32 chains per cluster (per vector component)
        float4 acc[KTILE];
#pragma unroll
        for (int k = 0; k < KTILE; k++) acc[k] = make_float4(0.f, 0.f, 0.f, 0.f);

        const float4* frow = F4 + pl * D4;
#pragma unroll 2
        for (int i = 0; i < D4; i++) {
            float4 x = frow[i];
#pragma unroll
            for (int k = 0; k < KTILE; k++) {
                float4 c = cs[k][i];
                acc[k].x = fmaf(x.x, c.x, acc[k].x);
                acc[k].y = fmaf(x.y, c.y, acc[k].y);
                acc[k].z = fmaf(x.z, c.z, acc[k].z);
                acc[k].w = fmaf(x.w, c.w, acc[k].w);
            }
        }

#pragma unroll
        for (int k = 0; k < KTILE; k++) {
            float cross = (acc[k].x + acc[k].y) + (acc[k].z + acc[k].w);
            // replicate reference elementwise fp32 ops exactly:
            // (x_sq + c_sq) - 2*cross, clamped at 0; sqrt is monotone -> skip
            float dj = fmaxf((xsq + scq[k0 + k]) - 2.0f * cross, 0.0f);
            if (dj < best) { best = dj; bidx = k0 + k; }
        }
    }

    if (valid) out[p] = (float)bidx;
}

// ---------------------------------------------------------------------------
extern "C" void kernel_launch(void* const* d_in, const int* in_sizes, int n_in,
                              void* d_out, int out_size) {
    // features is the LARGER tensor (262144*768 vs 500*768), order-agnostic.
    int i_f = 0, i_c = 1;
    if (n_in >= 2 && in_sizes[0] < in_sizes[1]) { i_f = 1; i_c = 0; }
    const float* F = (const float*)d_in[i_f];
    const float* C = (const float*)d_in[i_c];
    float* out = (float*)d_out;   // indices as float32 per __output__ dtype
    const int N = in_sizes[i_f] / DDIM;

    const int grid = (N + NTHR - 1) / NTHR;
    kmeans_simple_kernel<<<grid, NTHR>>>(F, C, out, N);
}

// round 11
// speedup vs baseline: 1.6633x; 1.6633x over previous
#include <cuda_runtime.h>
#include <cstdint>

#define DDIM 768
#define D4   192          // DDIM/4
#define KCL  500
#define KPAD 512
#define TM   128          // points per block
#define TN   64           // clusters per k0 tile
#define NK0  (KPAD / TN)  // 8 k0 tiles
#define TD   16           // d per chunk
#define NCH  (DDIM / TD)  // 48 chunks

__device__ float g_csq[KPAD];
__device__ float g_xsq[262144];

// ---- packed fp32x2 helpers -------------------------------------------------
__device__ __forceinline__ unsigned long long ffma2(unsigned long long a,
                                                    unsigned long long b,
                                                    unsigned long long c) {
    unsigned long long d;
    asm("fma.rn.f32x2 %0, %1, %2, %3;" : "=l"(d) : "l"(a), "l"(b), "l"(c));
    return d;
}
__device__ __forceinline__ float2 unpack2(unsigned long long v) {
    unsigned int lo, hi;
    asm("mov.b64 {%0, %1}, %2;" : "=r"(lo), "=r"(hi) : "l"(v));
    return make_float2(__uint_as_float(lo), __uint_as_float(hi));
}

// ---- warp-per-row squared norms, fp32 squares summed in fp64 ---------------
__device__ __forceinline__ float row_sqnorm(const float4* row4, int lane) {
    double s = 0.0;
#pragma unroll
    for (int i = 0; i < 6; i++) {
        float4 v = row4[i * 32 + lane];
        s += (double)(v.x * v.x); s += (double)(v.y * v.y);
        s += (double)(v.z * v.z); s += (double)(v.w * v.w);
    }
#pragma unroll
    for (int o = 16; o > 0; o >>= 1)
        s += __shfl_down_sync(0xFFFFFFFFu, s, o);
    return (float)s;
}

__global__ void csq_kernel(const float* __restrict__ C) {
    int w = (blockIdx.x * blockDim.x + threadIdx.x) >> 5;
    int lane = threadIdx.x & 31;
    if (w >= KPAD) return;
    float r = 1e30f;
    if (w < KCL) r = row_sqnorm((const float4*)C + (long)w * D4, lane);
    if (lane == 0) g_csq[w] = r;
}

__global__ void xsq_kernel(const float* __restrict__ F, int N) {
    int w = (blockIdx.x * blockDim.x + threadIdx.x) >> 5;
    int lane = threadIdx.x & 31;
    if (w >= N) return;
    float r = row_sqnorm((const float4*)F + (long)w * D4, lane);
    if (lane == 0) g_xsq[w] = r;
}

// ---- main fused GEMM + argmin ----------------------------------------------
__global__ __launch_bounds__(256, 2)
void kmeans_tiled_kernel(const float* __restrict__ F,
                         const float* __restrict__ C,
                         float* __restrict__ out, int N) {
    __shared__ __align__(16) float2 As2[8][132];  // (d,d+1) pairs, row-indexed
    __shared__ __align__(16) float2 Bs2[8][66];   // (d,d+1) pairs, col-indexed
    __shared__ float s_csq[KPAD];
    __shared__ float s_xsq[TM];
    __shared__ float s_redv[TM][16];
    __shared__ int   s_redi[TM][16];
    __shared__ float s_bestv[TM];
    __shared__ int   s_besti[TM];

    const int t  = threadIdx.x;
    const int ty = t >> 4;          // 0..15 : 8 rows each
    const int tx = t & 15;          // 0..15 : cols {tx, tx+16, tx+32, tx+48}
    const int row0 = blockIdx.x * TM;

    // A-slot mapping (512 float4 slots, 2 per thread), B-slot (256, 1/thread)
    const int ar0 = t >> 2,          ac0 = t & 3;
    const int ar1 = (t + 256) >> 2,  ac1 = t & 3;
    const int br  = t >> 2,          bc  = t & 3;

    const float4* F4 = (const float4*)F;
    const float4* C4 = (const float4*)C;

    if (t < 256) { s_csq[t] = g_csq[t]; s_csq[t + 256] = g_csq[t + 256]; }
    if (t < TM)  { s_xsq[t] = g_xsq[row0 + t]; s_bestv[t] = 3.4e38f; s_besti[t] = 0x7FFFFFFF; }
    __syncthreads();

    for (int k0 = 0; k0 < KPAD; k0 += TN) {
        unsigned long long acc[8][4];
#pragma unroll
        for (int i = 0; i < 8; i++)
#pragma unroll
            for (int q = 0; q < 4; q++) acc[i][q] = 0ULL;

        // prefetch chunk 0
        float4 pa0 = F4[(long)(row0 + ar0) * D4 + ac0];
        float4 pa1 = F4[(long)(row0 + ar1) * D4 + ac1];
        float4 pb  = (k0 + br < KCL) ? C4[(long)(k0 + br) * D4 + bc]
                                     : make_float4(0.f, 0.f, 0.f, 0.f);

#pragma unroll 1
        for (int c = 0; c < NCH; c++) {
            __syncthreads();
            As2[ac0 * 2 + 0][ar0] = make_float2(pa0.x, pa0.y);
            As2[ac0 * 2 + 1][ar0] = make_float2(pa0.z, pa0.w);
            As2[ac1 * 2 + 0][ar1] = make_float2(pa1.x, pa1.y);
            As2[ac1 * 2 + 1][ar1] = make_float2(pa1.z, pa1.w);
            Bs2[bc  * 2 + 0][br ] = make_float2(pb.x, pb.y);
            Bs2[bc  * 2 + 1][br ] = make_float2(pb.z, pb.w);
            __syncthreads();

            if (c + 1 < NCH) {
                const int dc = (c + 1) * 4;
                pa0 = F4[(long)(row0 + ar0) * D4 + dc + ac0];
                pa1 = F4[(long)(row0 + ar1) * D4 + dc + ac1];
                pb  = (k0 + br < KCL) ? C4[(long)(k0 + br) * D4 + dc + bc]
                                      : make_float4(0.f, 0.f, 0.f, 0.f);
            }

#pragma unroll
            for (int dp = 0; dp < 8; dp++) {
                ulonglong2 a01 = *(const ulonglong2*)&As2[dp][ty * 8 + 0];
                ulonglong2 a23 = *(const ulonglong2*)&As2[dp][ty * 8 + 2];
                ulonglong2 a45 = *(const ulonglong2*)&As2[dp][ty * 8 + 4];
                ulonglong2 a67 = *(const ulonglong2*)&As2[dp][ty * 8 + 6];
                unsigned long long ap[8] = {a01.x, a01.y, a23.x, a23.y,
                                            a45.x, a45.y, a67.x, a67.y};
                unsigned long long bq[4];
#pragma unroll
                for (int q = 0; q < 4; q++)
                    bq[q] = *(const unsigned long long*)&Bs2[dp][tx + 16 * q];
#pragma unroll
                for (int i = 0; i < 8; i++)
#pragma unroll
                    for (int q = 0; q < 4; q++)
                        acc[i][q] = ffma2(ap[i], bq[q], acc[i][q]);
            }
        }

        // ---- epilogue for this k0 tile ----
#pragma unroll
        for (int i = 0; i < 8; i++) {
            const int r = ty * 8 + i;
            const float xs = s_xsq[r];
            float rv = 3.4e38f; int ri = 0x7FFFFFFF;
#pragma unroll
            for (int q = 0; q < 4; q++) {
                float2 v = unpack2(acc[i][q]);
                float cross = v.x + v.y;
                int col = k0 + tx + 16 * q;
                float dj = fmaxf((xs + s_csq[col]) - 2.0f * cross, 0.0f);
                if (dj < rv || (dj == rv && col < ri)) { rv = dj; ri = col; }
            }
            s_redv[r][tx] = rv;
            s_redi[r][tx] = ri;
        }
        __syncthreads();

        if (t < TM) {
            float bv = s_bestv[t]; int bi = s_besti[t];
#pragma unroll
            for (int x = 0; x < 16; x++) {
                float v = s_redv[t][x]; int idx = s_redi[t][x];
                if (v < bv || (v == bv && idx < bi)) { bv = v; bi = idx; }
            }
            s_bestv[t] = bv; s_besti[t] = bi;
        }
        __syncthreads();
    }

    if (t < TM) out[row0 + t] = (float)s_besti[t];
}

// ---------------------------------------------------------------------------
extern "C" void kernel_launch(void* const* d_in, const int* in_sizes, int n_in,
                              void* d_out, int out_size) {
    int i_f = 0, i_c = 1;
    if (n_in >= 2 && in_sizes[0] < in_sizes[1]) { i_f = 1; i_c = 0; }
    const float* F = (const float*)d_in[i_f];
    const float* C = (const float*)d_in[i_c];
    float* out = (float*)d_out;
    const int N = in_sizes[i_f] / DDIM;

    csq_kernel<<<(KPAD * 32 + 255) / 256, 256>>>(C);
    xsq_kernel<<<(N * 32 + 255) / 256, 256>>>(F, N);
    kmeans_tiled_kernel<<<N / TM, 256>>>(F, C, out, N);
}

// round 17
// speedup vs baseline: 3.7751x; 2.2696x over previous
#include <cuda_runtime.h>
#include <cuda_bf16.h>
#include <cstdint>

#define DDIM 768
#define D4   192
#define KCL  500
#define KPAD 512
#define NMAX 262144
#define MT   128          // points per block
#define NT   128          // clusters per k0 tile
#define KCH  16           // k per chunk
#define NCH  (DDIM / KCH) // 48
#define TAU  0.05f

__device__ float g_csq[KPAD];
__device__ float g_xsq[NMAX];
__device__ unsigned short g_Bh[KPAD * DDIM];
__device__ unsigned short g_Bl[KPAD * DDIM];
__device__ unsigned short g_Fh[(size_t)NMAX * DDIM];
__device__ unsigned short g_Fl[(size_t)NMAX * DDIM];

// smem word swizzle: conflict-free for frag loads (w in {t, t+4}) AND
// chunk stores (w in {2q, 2q+1}); x(r) xor-differs by 5 between r and r+4.
__device__ __forceinline__ int swz(int r) {
    int r3 = r & 7;
    return (r3 & 3) ^ ((r3 >> 2) * 5);
}

__device__ __forceinline__ void mma16816(float* c, const uint32_t* a,
                                         const uint32_t* b) {
    asm volatile(
        "mma.sync.aligned.m16n8k16.row.col.f32.bf16.bf16.f32 "
        "{%0,%1,%2,%3}, {%4,%5,%6,%7}, {%8,%9}, {%0,%1,%2,%3};"
        : "+f"(c[0]), "+f"(c[1]), "+f"(c[2]), "+f"(c[3])
        : "r"(a[0]), "r"(a[1]), "r"(a[2]), "r"(a[3]), "r"(b[0]), "r"(b[1]));
}

// ---------------------------------------------------------------------------
// prep kernels
// ---------------------------------------------------------------------------
__device__ __forceinline__ float row_sqnorm(const float4* row4, int lane) {
    double s = 0.0;
#pragma unroll
    for (int i = 0; i < 6; i++) {
        float4 v = row4[i * 32 + lane];
        s += (double)(v.x * v.x); s += (double)(v.y * v.y);
        s += (double)(v.z * v.z); s += (double)(v.w * v.w);
    }
#pragma unroll
    for (int o = 16; o > 0; o >>= 1) s += __shfl_down_sync(0xFFFFFFFFu, s, o);
    return (float)s;
}

__global__ void csq_kernel(const float* __restrict__ C) {
    int w = (blockIdx.x * blockDim.x + threadIdx.x) >> 5;
    int lane = threadIdx.x & 31;
    if (w >= KPAD) return;
    float r = 1e30f;
    if (w < KCL) r = row_sqnorm((const float4*)C + (long)w * D4, lane);
    if (lane == 0) g_csq[w] = r;
}

__global__ void xsq_kernel(const float* __restrict__ F, int N) {
    int w = (blockIdx.x * blockDim.x + threadIdx.x) >> 5;
    int lane = threadIdx.x & 31;
    if (w >= N) return;
    float r = row_sqnorm((const float4*)F + (long)w * D4, lane);
    if (lane == 0) g_xsq[w] = r;
}

__global__ void bconv_kernel(const float* __restrict__ C) {
    int i = blockIdx.x * blockDim.x + threadIdx.x;
    if (i >= KPAD * DDIM) return;
    int k = i / DDIM, d = i - k * DDIM;
    float a = (k < KCL) ? C[(long)k * DDIM + d] : 0.0f;
    __nv_bfloat16 h = __float2bfloat16(a);
    float r = a - __bfloat162float(h);
    g_Bh[i] = __bfloat16_as_ushort(h);
    g_Bl[i] = __bfloat16_as_ushort(__float2bfloat16(r));
}

__global__ void fconv_kernel(const float* __restrict__ F, int N) {
    long i = (long)blockIdx.x * blockDim.x + threadIdx.x;   // float4 index
    if (i >= (long)N * D4) return;
    float4 v = ((const float4*)F)[i];
    __nv_bfloat16 h0 = __float2bfloat16(v.x), h1 = __float2bfloat16(v.y);
    __nv_bfloat16 h2 = __float2bfloat16(v.z), h3 = __float2bfloat16(v.w);
    float r0 = v.x - __bfloat162float(h0), r1 = v.y - __bfloat162float(h1);
    float r2 = v.z - __bfloat162float(h2), r3 = v.w - __bfloat162float(h3);
    ushort4 hv, lv;
    hv.x = __bfloat16_as_ushort(h0); hv.y = __bfloat16_as_ushort(h1);
    hv.z = __bfloat16_as_ushort(h2); hv.w = __bfloat16_as_ushort(h3);
    lv.x = __bfloat16_as_ushort(__float2bfloat16(r0));
    lv.y = __bfloat16_as_ushort(__float2bfloat16(r1));
    lv.z = __bfloat16_as_ushort(__float2bfloat16(r2));
    lv.w = __bfloat16_as_ushort(__float2bfloat16(r3));
    ((ushort4*)g_Fh)[i] = hv;
    ((ushort4*)g_Fl)[i] = lv;
}

// ---------------------------------------------------------------------------
// main: mma.sync bf16x3 GEMM + fused argmin with (best, second) margin
// ---------------------------------------------------------------------------
__global__ __launch_bounds__(256, 1)
void kmeans_mma_kernel(float* __restrict__ out, int N) {
    __shared__ uint32_t sAh[1024], sAl[1024], sBh[1024], sBl[1024];
    __shared__ float s_csq[KPAD];
    __shared__ float s_xsq[MT];
    __shared__ float s_redv[MT][4], s_red2[MT][4];
    __shared__ int   s_redi[MT][4];
    __shared__ float s_bestv[MT], s_best2[MT];
    __shared__ int   s_besti[MT];

    const int t = threadIdx.x;
    const int wid = t >> 5, lane = t & 31;
    const int warp_m = wid >> 2, warp_n = wid & 3;
    const int g = lane >> 2, tq = lane & 3;
    const int xg = swz(g);
    const int w0x = tq ^ xg;          // frag word for k 0-7
    const int w1x = w0x ^ 4;          // frag word for k 8-15
    const int row0 = blockIdx.x * MT;

    s_csq[t] = g_csq[t];
    s_csq[t + 256] = g_csq[t + 256];
    if (t < MT) {
        s_xsq[t] = g_xsq[row0 + t];
        s_bestv[t] = 3.4e38f; s_best2[t] = 3.4e38f; s_besti[t] = 0x7FFFFFFF;
    }
    __syncthreads();

    // loader mapping: slots s0 = t, s1 = t+256; row = s>>2, q = s&3
    const int r0_ = t >> 2,         q0 = t & 3;
    const int r1_ = (t + 256) >> 2, q1 = t & 3;
    const int x0 = swz(r0_), x1 = swz(r1_);
    const int si00 = r0_ * 8 + ((2 * q0) ^ x0), si01 = r0_ * 8 + ((2 * q0 + 1) ^ x0);
    const int si10 = r1_ * 8 + ((2 * q1) ^ x1), si11 = r1_ * 8 + ((2 * q1 + 1) ^ x1);
    const long aoff0 = (long)(row0 + r0_) * D4 + q0;   // uint2 units
    const long aoff1 = (long)(row0 + r1_) * D4 + q1;
    const long boff0 = (long)r0_ * D4 + q0;
    const long boff1 = (long)r1_ * D4 + q1;

    const uint2* Fh2 = (const uint2*)g_Fh;
    const uint2* Fl2 = (const uint2*)g_Fl;
    const uint2* Bh2 = (const uint2*)g_Bh;
    const uint2* Bl2 = (const uint2*)g_Bl;

#pragma unroll 1
    for (int k0t = 0; k0t < 4; k0t++) {
        const int k0 = k0t * NT;
        const long bb = (long)k0 * D4;

        float acc[4][4][4];
#pragma unroll
        for (int i = 0; i < 4; i++)
#pragma unroll
            for (int j = 0; j < 4; j++)
#pragma unroll
                for (int r = 0; r < 4; r++) acc[i][j][r] = 0.0f;

        uint2 pAh0 = Fh2[aoff0], pAh1 = Fh2[aoff1];
        uint2 pAl0 = Fl2[aoff0], pAl1 = Fl2[aoff1];
        uint2 pBh0 = Bh2[bb + boff0], pBh1 = Bh2[bb + boff1];
        uint2 pBl0 = Bl2[bb + boff0], pBl1 = Bl2[bb + boff1];

#pragma unroll 1
        for (int c = 0; c < NCH; c++) {
            __syncthreads();
            sAh[si00] = pAh0.x; sAh[si01] = pAh0.y; sAh[si10] = pAh1.x; sAh[si11] = pAh1.y;
            sAl[si00] = pAl0.x; sAl[si01] = pAl0.y; sAl[si10] = pAl1.x; sAl[si11] = pAl1.y;
            sBh[si00] = pBh0.x; sBh[si01] = pBh0.y; sBh[si10] = pBh1.x; sBh[si11] = pBh1.y;
            sBl[si00] = pBl0.x; sBl[si01] = pBl0.y; sBl[si10] = pBl1.x; sBl[si11] = pBl1.y;
            __syncthreads();

            if (c + 1 < NCH) {
                const long dc = (long)(c + 1) * 4;
                pAh0 = Fh2[aoff0 + dc]; pAh1 = Fh2[aoff1 + dc];
                pAl0 = Fl2[aoff0 + dc]; pAl1 = Fl2[aoff1 + dc];
                pBh0 = Bh2[bb + boff0 + dc]; pBh1 = Bh2[bb + boff1 + dc];
                pBl0 = Bl2[bb + boff0 + dc]; pBl1 = Bl2[bb + boff1 + dc];
            }

            // B fragments for this warp's 4 n-tiles
            uint32_t bh[4][2], bl[4][2];
#pragma unroll
            for (int nt = 0; nt < 4; nt++) {
                const int rB = warp_n * 32 + nt * 8 + g;
                bh[nt][0] = sBh[rB * 8 + w0x]; bh[nt][1] = sBh[rB * 8 + w1x];
                bl[nt][0] = sBl[rB * 8 + w0x]; bl[nt][1] = sBl[rB * 8 + w1x];
            }

#pragma unroll
            for (int mt = 0; mt < 4; mt++) {
                const int r1 = warp_m * 64 + mt * 16 + g;
                const int r2 = r1 + 8;
                uint32_t ah[4], al[4];
                ah[0] = sAh[r1 * 8 + w0x]; ah[1] = sAh[r2 * 8 + w0x];
                ah[2] = sAh[r1 * 8 + w1x]; ah[3] = sAh[r2 * 8 + w1x];
                al[0] = sAl[r1 * 8 + w0x]; al[1] = sAl[r2 * 8 + w0x];
                al[2] = sAl[r1 * 8 + w1x]; al[3] = sAl[r2 * 8 + w1x];
#pragma unroll
                for (int nt = 0; nt < 4; nt++) {
                    mma16816(acc[mt][nt], ah, bh[nt]);   // hi*hi
                    mma16816(acc[mt][nt], ah, bl[nt]);   // hi*lo
                    mma16816(acc[mt][nt], al, bh[nt]);   // lo*hi
                }
            }
        }

        // ---- epilogue for this k0 tile ----
#pragma unroll
        for (int mt = 0; mt < 4; mt++) {
#pragma unroll
            for (int half = 0; half < 2; half++) {
                const int r = warp_m * 64 + mt * 16 + g + half * 8;
                const float xs = s_xsq[r];
                float bv = 3.4e38f, b2 = 3.4e38f; int bi = 0x7FFFFFFF;
#pragma unroll
                for (int nt = 0; nt < 4; nt++) {
#pragma unroll
                    for (int j = 0; j < 2; j++) {
                        const int col = k0 + warp_n * 32 + nt * 8 + tq * 2 + j;
                        const float cross = acc[mt][nt][half * 2 + j];
                        const float dj = fmaxf((xs + s_csq[col]) - 2.0f * cross, 0.0f);
                        if (dj < bv || (dj == bv && col < bi)) { b2 = bv; bv = dj; bi = col; }
                        else if (dj < b2) b2 = dj;
                    }
                }
                // quad reduce over tq (lanes xor 1, 2)
#pragma unroll
                for (int off = 1; off <= 2; off <<= 1) {
                    float ov = __shfl_xor_sync(0xFFFFFFFFu, bv, off);
                    int   oi = __shfl_xor_sync(0xFFFFFFFFu, bi, off);
                    float o2 = __shfl_xor_sync(0xFFFFFFFFu, b2, off);
                    bool better = (ov < bv) || (ov == bv && oi < bi);
                    float nb = better ? ov : bv;
                    int   ni = better ? oi : bi;
                    float n2 = fminf(fminf(b2, o2), better ? bv : ov);
                    bv = nb; bi = ni; b2 = n2;
                }
                if (tq == 0) {
                    s_redv[r][warp_n] = bv; s_red2[r][warp_n] = b2; s_redi[r][warp_n] = bi;
                }
            }
        }
        __syncthreads();

        if (t < MT) {
            float bv = s_bestv[t], b2 = s_best2[t]; int bi = s_besti[t];
#pragma unroll
            for (int x = 0; x < 4; x++) {
                float ov = s_redv[t][x], o2 = s_red2[t][x]; int oi = s_redi[t][x];
                bool better = (ov < bv) || (ov == bv && oi < bi);
                float nb = better ? ov : bv;
                int   ni = better ? oi : bi;
                float n2 = fminf(fminf(b2, o2), better ? bv : ov);
                bv = nb; bi = ni; b2 = n2;
            }
            s_bestv[t] = bv; s_best2[t] = b2; s_besti[t] = bi;
        }
        __syncthreads();
    }

    if (t < MT) {
        float margin = s_best2[t] - s_bestv[t];
        out[row0 + t] = (margin > TAU) ? (float)s_besti[t] : -1.0f;
    }
}

// ---------------------------------------------------------------------------
// rescue: warp per flagged point; round-10-exact math
// ---------------------------------------------------------------------------
__global__ __launch_bounds__(256)
void rescue_kernel(const float* __restrict__ F, const float* __restrict__ C,
                   float* __restrict__ out, int N) {
    int gw = (blockIdx.x * blockDim.x + threadIdx.x) >> 5;
    int lane = threadIdx.x & 31;
    if (gw >= N) return;
    if (out[gw] >= 0.0f) return;

    const float4* fr = (const float4*)F + (long)gw * D4;
    const float xs = g_xsq[gw];
    float bv = 3.4e38f; int bi = 0x7FFFFFFF;

    for (int k = lane; k < KCL; k += 32) {
        const float4* cr = (const float4*)C + (long)k * D4;
        float ax = 0.f, ay = 0.f, az = 0.f, aw = 0.f;
#pragma unroll 8
        for (int i = 0; i < D4; i++) {
            float4 x = fr[i], cc = cr[i];
            ax = fmaf(x.x, cc.x, ax); ay = fmaf(x.y, cc.y, ay);
            az = fmaf(x.z, cc.z, az); aw = fmaf(x.w, cc.w, aw);
        }
        float cross = (ax + ay) + (az + aw);
        float dj = fmaxf((xs + g_csq[k]) - 2.0f * cross, 0.0f);
        if (dj < bv || (dj == bv && k < bi)) { bv = dj; bi = k; }
    }
#pragma unroll
    for (int o = 16; o > 0; o >>= 1) {
        float ov = __shfl_down_sync(0xFFFFFFFFu, bv, o);
        int   oi = __shfl_down_sync(0xFFFFFFFFu, bi, o);
        if (ov < bv || (ov == bv && oi < bi)) { bv = ov; bi = oi; }
    }
    if (lane == 0) out[gw] = (float)bi;
}

// ---------------------------------------------------------------------------
extern "C" void kernel_launch(void* const* d_in, const int* in_sizes, int n_in,
                              void* d_out, int out_size) {
    int i_f = 0, i_c = 1;
    if (n_in >= 2 && in_sizes[0] < in_sizes[1]) { i_f = 1; i_c = 0; }
    const float* F = (const float*)d_in[i_f];
    const float* C = (const float*)d_in[i_c];
    float* out = (float*)d_out;
    const int N = in_sizes[i_f] / DDIM;

    csq_kernel<<<(KPAD * 32) / 256, 256>>>(C);
    xsq_kernel<<<(N * 32 + 255) / 256, 256>>>(F, N);
    bconv_kernel<<<(KPAD * DDIM + 255) / 256, 256>>>(C);
    fconv_kernel<<<(int)(((long)N * D4 + 255) / 256), 256>>>(F, N);
    kmeans_mma_kernel<<<N / MT, 256>>>(out, N);
    rescue_kernel<<<(N * 32 + 255) / 256, 256>>>(F, C, out, N);
}